// round 16
// baseline (speedup 1.0000x reference)
#include <cuda_runtime.h>
#include <cuda_fp16.h>
#include <math.h>

#define NN 4096
#define NMASK (NN - 1)
#define INC 512
#define HID 64
#define HEADS 8
#define OUTC 256
#define WPR 128               // bitmap words per row (4096/32)
#define EMAX 131072
#define EPMAX (EMAX + NN)

// ------------------------- device scratch (no allocs allowed) -------------------------
// NOTE: bitmaps + cnt/scnt are zero-initialized at module load and re-zeroed at the
// TAIL of every kernel_launch (k_zero_small), so each run starts clean.
__device__ unsigned g_bmA[NN * WPR];    // adjacency bitmap, row = src
__device__ unsigned g_bmAT[NN * WPR];   // transpose bitmap, row = dst
__device__ int      g_cnt[NN];          // in-degree with duplicates (dst-sorted CSR)
__device__ int      g_scnt[NN];         // out-degree with duplicates (src-sorted CSR)
__device__ int      g_rowptr[NN + 1];
__device__ int      g_cursor[NN];
__device__ int      g_sptr[NN + 1];
__device__ int      g_scursor[NN];
__device__ int      g_srcS[EPMAX];      // edges sorted by dst: src id
__device__ int      g_dstS[EPMAX];      // edges sorted by dst: dst id
__device__ int      g_dS[EPMAX];        // edges sorted by src: dst id
__device__ int      g_eidS[EPMAX];      // edges sorted by src: dst-sorted position
__device__ int      g_odeg[NN], g_ideg[NN];
__device__ int      g_optr[NN + 1], g_iptr[NN + 1];
__device__ int      g_oCSR[EPMAX];      // deduped out-neighbors
__device__ int      g_iCSR[EPMAX];      // deduped in-neighbors
__device__ float    g_r1[NN], g_r2[NN], g_r3[NN];
__device__ float    g_h1[NN * INC];
__device__ __half   g_h1h[NN * INC];    // fp16 shadow of h1 for the agg1 gather
__device__ float    g_act1[NN * INC];
__device__ float    g_h2[NN * OUTC];
__device__ float    g_res[NN * OUTC];
__device__ float    g_ss1[NN * HEADS], g_sd1[NN * HEADS];
__device__ float    g_ss2[NN], g_sd2[NN];
__device__ float    g_eraw1[HEADS * EPMAX];   // [head][edge] planes
__device__ float    g_alpha1[HEADS * EPMAX];  // [head][edge] planes
__device__ float    g_mw[EPMAX];
__device__ float    g_eraw2[EPMAX];
__device__ float    g_alpha2[EPMAX];

// ------------------------- zero kernel (vectorized; runs at TAIL) -------------------------
__global__ void k_zero_small() {
    int i = blockIdx.x * blockDim.x + threadIdx.x;   // 131072 threads
    uint4 z = make_uint4(0u, 0u, 0u, 0u);
    reinterpret_cast<uint4*>(g_bmA)[i] = z;
    reinterpret_cast<uint4*>(g_bmAT)[i] = z;
    if (i < NN) { g_cnt[i] = 0; g_scnt[i] = 0; }
}

// ------------------------- graph build -------------------------
__global__ void k_build(const int* __restrict__ src32,
                        const int* __restrict__ dst32, int E) {
    int i = blockIdx.x * blockDim.x + threadIdx.x;
    int EP = E + NN;
    if (i >= EP) return;
    int s, d;
    if (i < E) { s = src32[i] & NMASK; d = dst32[i] & NMASK; }
    else       { s = d = i - E; }                    // self loops
    atomicOr(&g_bmA[s * WPR + (d >> 5)], 1u << (d & 31));
    atomicOr(&g_bmAT[d * WPR + (s >> 5)], 1u << (s & 31));
    atomicAdd(&g_cnt[d], 1);
    atomicAdd(&g_scnt[s], 1);
}

// degrees from bitmaps, warp per node, one uint4 per lane (coalesced)
__global__ void k_deg() {
    int n = blockIdx.x * (blockDim.x >> 5) + (threadIdx.x >> 5);
    int lane = threadIdx.x & 31;
    if (n >= NN) return;
    uint4 a = reinterpret_cast<const uint4*>(&g_bmA[n * WPR])[lane];
    uint4 b = reinterpret_cast<const uint4*>(&g_bmAT[n * WPR])[lane];
    int co = __popc(a.x) + __popc(a.y) + __popc(a.z) + __popc(a.w);
    int ci = __popc(b.x) + __popc(b.y) + __popc(b.z) + __popc(b.w);
#pragma unroll
    for (int o = 16; o; o >>= 1) {
        co += __shfl_down_sync(0xffffffffu, co, o);
        ci += __shfl_down_sync(0xffffffffu, ci, o);
    }
    if (lane == 0) {
        g_odeg[n] = co;
        g_ideg[n] = ci;
        g_r1[n] = (float)co;
    }
}

// paired scans. WHICH=0: {cnt->rowptr/cursor, scnt->sptr/scursor}. WHICH=1: {odeg->optr, ideg->iptr}.
template <int WHICH>
__global__ void k_scan2() {
    const int* in;
    int* ptr;
    int* cur;
    if (WHICH == 0) {
        if (blockIdx.x == 0) { in = g_cnt;  ptr = g_rowptr; cur = g_cursor; }
        else                 { in = g_scnt; ptr = g_sptr;   cur = g_scursor; }
    } else {
        if (blockIdx.x == 0) { in = g_odeg; ptr = g_optr;   cur = 0; }
        else                 { in = g_ideg; ptr = g_iptr;   cur = 0; }
    }
    __shared__ int sh[1024];
    int t = threadIdx.x;
    int v[4]; int s = 0;
#pragma unroll
    for (int i = 0; i < 4; i++) { v[i] = in[t * 4 + i]; s += v[i]; }
    sh[t] = s;
    __syncthreads();
    for (int off = 1; off < 1024; off <<= 1) {
        int x = (t >= off) ? sh[t - off] : 0;
        __syncthreads();
        sh[t] += x;
        __syncthreads();
    }
    int run = (t == 0) ? 0 : sh[t - 1];
#pragma unroll
    for (int i = 0; i < 4; i++) {
        ptr[t * 4 + i] = run;
        if (cur) cur[t * 4 + i] = run;
        run += v[i];
    }
    if (t == 1023) ptr[NN] = sh[1023];
}

// both counting-sort scatters in one pass; link src-order entry to dst-order pos
__global__ void k_scatter(const int* __restrict__ src32,
                          const int* __restrict__ dst32, int E) {
    int i = blockIdx.x * blockDim.x + threadIdx.x;
    int EP = E + NN;
    if (i >= EP) return;
    int s, d;
    if (i < E) { s = src32[i] & NMASK; d = dst32[i] & NMASK; }
    else       { s = d = i - E; }
    int posD = atomicAdd(&g_cursor[d], 1);
    g_srcS[posD] = s;
    g_dstS[posD] = d;
    int posS = atomicAdd(&g_scursor[s], 1);
    g_dS[posS] = d;
    g_eidS[posS] = posD;
}

// fill deduped CSRs from bitmaps. block per node, thread per word.
__global__ void k_csr_fill() {
    __shared__ int oc, ic;
    int n = blockIdx.x, w = threadIdx.x;
    if (w == 0) { oc = g_optr[n]; ic = g_iptr[n]; }
    __syncthreads();
    unsigned bits = g_bmA[n * WPR + w];
    int c = __popc(bits);
    int p = atomicAdd(&oc, c);
    while (bits) {
        int j = w * 32 + __ffs(bits) - 1;
        bits &= bits - 1;
        g_oCSR[p++] = j;
    }
    bits = g_bmAT[n * WPR + w];
    c = __popc(bits);
    p = atomicAdd(&ic, c);
    while (bits) {
        int j = w * 32 + __ffs(bits) - 1;
        bits &= bits - 1;
        g_iCSR[p++] = j;
    }
}

// ------------------------- motif path -------------------------
template <int PASS>
__global__ void k_spmv() {
    const float* rin  = (PASS == 0) ? g_r1 : g_r2;
    float*       rout = (PASS == 0) ? g_r2 : g_r3;
    int n = blockIdx.x * (blockDim.x >> 5) + (threadIdx.x >> 5);  // warp per node
    int lane = threadIdx.x & 31;
    if (n >= NN) return;
    int o0 = g_optr[n], nm = g_optr[n + 1] - o0;
    float acc = 0.f;
    for (int i = lane; i < nm; i += 32) acc += rin[g_oCSR[o0 + i]];
#pragma unroll
    for (int o = 16; o; o >>= 1) acc += __shfl_down_sync(0xffffffffu, acc, o);
    if (lane == 0) rout[n] = acc;
}

// Fused A^2-row + per-edge A^3: block per source s.
__global__ __launch_bounds__(256) void k_motif() {
    __shared__ int row[NN];    // 16KB
    int s = blockIdx.x;
    for (int i = threadIdx.x; i < NN; i += blockDim.x) row[i] = 0;
    __syncthreads();
    int warp = threadIdx.x >> 5, lane = threadIdx.x & 31;
    int nwarps = blockDim.x >> 5;
    int o0 = g_optr[s], nm = g_optr[s + 1] - o0;
    for (int i = warp; i < nm; i += nwarps) {
        int m = g_oCSR[o0 + i];
        int mo = g_optr[m], mn = g_optr[m + 1] - mo;
        for (int j = lane; j < mn; j += 32)
            atomicAdd(&row[g_oCSR[mo + j]], 1);
    }
    __syncthreads();
    float rs = g_r3[s];
    if (rs < 1.f) rs = 1.f;
    int e0 = g_sptr[s], ne = g_sptr[s + 1] - e0;
    for (int j = warp; j < ne; j += nwarps) {
        int d = g_dS[e0 + j];
        int i0 = g_iptr[d], nk = g_iptr[d + 1] - i0;
        int acc = 0;
        for (int i = lane; i < nk; i += 32) acc += row[g_iCSR[i0 + i]];
#pragma unroll
        for (int o = 16; o; o >>= 1) acc += __shfl_down_sync(0xffffffffu, acc, o);
        if (lane == 0) g_mw[g_eidS[e0 + j]] = (float)acc / rs;
    }
}

// ------------------------- TF32 tensor-core GEMM -------------------------
#define ASTR 36
#define BSTR 136

__device__ __forceinline__ unsigned f2tf32(float f) {
    unsigned u;
    asm("cvt.rna.tf32.f32 %0, %1;" : "=r"(u) : "f"(f));
    return u;
}

// layer 0: A=Aext(x), B=B0(W1), C=g_h1 (+fp16 shadow)
// layer 1: A=g_act1,  B=B0(W2), C=g_h2
// layer 2: A=g_act1,  B=B0(resW2), C=g_res
__global__ __launch_bounds__(256, 1) void k_gemm_tf32(
        const float* __restrict__ Aext,
        const float* __restrict__ B0,
        int layer, int Nn, int K) {
    const float* A;
    const float* B = B0;
    float* C;
    if (layer == 0)      { A = Aext;   C = g_h1; }
    else if (layer == 1) { A = g_act1; C = g_h2; }
    else                 { A = g_act1; C = g_res; }
    __shared__ unsigned As[2][128 * ASTR];
    __shared__ unsigned Bs[2][32 * BSTR];

    int tid = threadIdx.x;
    int lane = tid & 31;
    int warp = tid >> 5;
    int warpM = warp & 1;
    int warpN = warp >> 1;
    int bx = blockIdx.x * 128, by = blockIdx.y * 128;
    int grp = lane >> 2;
    int tig = lane & 3;

    float c[4][4][4];
#pragma unroll
    for (int mi = 0; mi < 4; mi++)
#pragma unroll
        for (int ni = 0; ni < 4; ni++)
#pragma unroll
            for (int r = 0; r < 4; r++) c[mi][ni][r] = 0.f;

    int arow[4], ac4[4], brow[4], bc4[4];
#pragma unroll
    for (int i = 0; i < 4; i++) {
        int idx = tid + i * 256;
        arow[i] = idx >> 3; ac4[i] = idx & 7;
        brow[i] = idx >> 5; bc4[i] = idx & 31;
    }

    auto stageStore = [&](int st, float4 va[4], float4 vb[4]) {
#pragma unroll
        for (int i = 0; i < 4; i++) {
            uint4 t;
            t.x = f2tf32(va[i].x); t.y = f2tf32(va[i].y);
            t.z = f2tf32(va[i].z); t.w = f2tf32(va[i].w);
            *(uint4*)&As[st][arow[i] * ASTR + ac4[i] * 4] = t;
            uint4 u;
            u.x = f2tf32(vb[i].x); u.y = f2tf32(vb[i].y);
            u.z = f2tf32(vb[i].z); u.w = f2tf32(vb[i].w);
            *(uint4*)&Bs[st][brow[i] * BSTR + bc4[i] * 4] = u;
        }
    };

    {
        float4 va[4], vb[4];
#pragma unroll
        for (int i = 0; i < 4; i++) {
            va[i] = *(const float4*)&A[(size_t)(by + arow[i]) * K + ac4[i] * 4];
            vb[i] = *(const float4*)&B[(size_t)brow[i] * Nn + bx + bc4[i] * 4];
        }
        stageStore(0, va, vb);
    }
    __syncthreads();

    int cur = 0;
    for (int k0 = 32; ; k0 += 32) {
        bool more = (k0 < K);
        float4 va[4], vb[4];
        if (more) {
#pragma unroll
            for (int i = 0; i < 4; i++) {
                va[i] = *(const float4*)&A[(size_t)(by + arow[i]) * K + k0 + ac4[i] * 4];
                vb[i] = *(const float4*)&B[(size_t)(k0 + brow[i]) * Nn + bx + bc4[i] * 4];
            }
        }
        const unsigned* as = As[cur];
        const unsigned* bs = Bs[cur];
#pragma unroll
        for (int kk = 0; kk < 32; kk += 8) {
            unsigned af[4][4], bf[4][2];
#pragma unroll
            for (int mi = 0; mi < 4; mi++) {
                int m = warpM * 64 + mi * 16 + grp;
                af[mi][0] = as[m * ASTR + kk + tig];
                af[mi][1] = as[(m + 8) * ASTR + kk + tig];
                af[mi][2] = as[m * ASTR + kk + tig + 4];
                af[mi][3] = as[(m + 8) * ASTR + kk + tig + 4];
            }
#pragma unroll
            for (int ni = 0; ni < 4; ni++) {
                int n = warpN * 32 + ni * 8 + grp;
                bf[ni][0] = bs[(kk + tig) * BSTR + n];
                bf[ni][1] = bs[(kk + tig + 4) * BSTR + n];
            }
#pragma unroll
            for (int mi = 0; mi < 4; mi++)
#pragma unroll
                for (int ni = 0; ni < 4; ni++) {
                    asm volatile(
                        "mma.sync.aligned.m16n8k8.row.col.f32.tf32.tf32.f32 "
                        "{%0,%1,%2,%3}, {%4,%5,%6,%7}, {%8,%9}, {%0,%1,%2,%3};"
                        : "+f"(c[mi][ni][0]), "+f"(c[mi][ni][1]),
                          "+f"(c[mi][ni][2]), "+f"(c[mi][ni][3])
                        : "r"(af[mi][0]), "r"(af[mi][1]),
                          "r"(af[mi][2]), "r"(af[mi][3]),
                          "r"(bf[ni][0]), "r"(bf[ni][1]));
                }
        }
        if (!more) break;
        stageStore(cur ^ 1, va, vb);
        __syncthreads();
        cur ^= 1;
    }

#pragma unroll
    for (int mi = 0; mi < 4; mi++) {
        int m0 = by + warpM * 64 + mi * 16 + grp;
#pragma unroll
        for (int ni = 0; ni < 4; ni++) {
            int n0 = bx + warpN * 32 + ni * 8 + 2 * tig;
            *(float2*)&C[(size_t)m0 * Nn + n0] = make_float2(c[mi][ni][0], c[mi][ni][1]);
            *(float2*)&C[(size_t)(m0 + 8) * Nn + n0] = make_float2(c[mi][ni][2], c[mi][ni][3]);
            if (layer == 0) {   // fp16 shadow of h1 for agg1 gather
                *(__half2*)&g_h1h[(size_t)m0 * INC + n0] =
                    __floats2half2_rn(c[mi][ni][0], c[mi][ni][1]);
                *(__half2*)&g_h1h[(size_t)(m0 + 8) * INC + n0] =
                    __floats2half2_rn(c[mi][ni][2], c[mi][ni][3]);
            }
        }
    }
}

// ------------------------- attention layer 1 -------------------------
__global__ void k_scores1(const float* __restrict__ as1, const float* __restrict__ ad1) {
    int idx = blockIdx.x * (blockDim.x >> 5) + (threadIdx.x >> 5);  // warp per (n,h)
    int lane = threadIdx.x & 31;
    if (idx >= NN * HEADS) return;
    int n = idx >> 3, h = idx & 7;
    const float* row = &g_h1[n * INC + h * HID];
    float a = 0.f, b = 0.f;
    for (int c = lane; c < HID; c += 32) {
        float v = row[c];
        a += v * as1[h * HID + c];
        b += v * ad1[h * HID + c];
    }
#pragma unroll
    for (int o = 16; o; o >>= 1) {
        a += __shfl_down_sync(0xffffffffu, a, o);
        b += __shfl_down_sync(0xffffffffu, b, o);
    }
    if (lane == 0) { g_ss1[idx] = a; g_sd1[idx] = b; }
}

// thread per edge; writes 8 head-planes (coalesced within each plane)
__global__ void k_eraw1(int EP) {
    int e = blockIdx.x * blockDim.x + threadIdx.x;
    if (e >= EP) return;
    int s = g_srcS[e], d = g_dstS[e];
    float4 sa = *(const float4*)&g_ss1[s * HEADS];
    float4 sb = *(const float4*)&g_ss1[s * HEADS + 4];
    float4 da = *(const float4*)&g_sd1[d * HEADS];
    float4 db = *(const float4*)&g_sd1[d * HEADS + 4];
    g_eraw1[0 * EPMAX + e] = sa.x + da.x;
    g_eraw1[1 * EPMAX + e] = sa.y + da.y;
    g_eraw1[2 * EPMAX + e] = sa.z + da.z;
    g_eraw1[3 * EPMAX + e] = sa.w + da.w;
    g_eraw1[4 * EPMAX + e] = sb.x + db.x;
    g_eraw1[5 * EPMAX + e] = sb.y + db.y;
    g_eraw1[6 * EPMAX + e] = sb.z + db.z;
    g_eraw1[7 * EPMAX + e] = sb.w + db.w;
}

__device__ __forceinline__ float lrelu(float x) { return x > 0.f ? x : 0.2f * x; }

// h-major thread mapping: consecutive threads -> consecutive d, same head plane.
__global__ void k_softmax1() {
    int idx = blockIdx.x * blockDim.x + threadIdx.x;
    if (idx >= NN * HEADS) return;
    int h = idx >> 12;            // idx / NN
    int d = idx & NMASK;
    const float* er1 = &g_eraw1[h * EPMAX];
    float* al1 = &g_alpha1[h * EPMAX];
    int r0 = g_rowptr[d], r1e = g_rowptr[d + 1];
    float mf = -1e30f, mm = -1e30f;
    for (int k = r0; k < r1e; k++) {
        float er = er1[k];
        float w = g_mw[k];
        mf = fmaxf(mf, lrelu(er));
        mm = fmaxf(mm, lrelu(er * w));
    }
    float sf = 0.f, sm = 0.f;
    for (int k = r0; k < r1e; k++) {
        float er = er1[k];
        float w = g_mw[k];
        sf += expf(lrelu(er) - mf);
        sm += expf(lrelu(er * w) - mm);
    }
    float isf = 1.f / (sf + 1e-16f), ism = 1.f / (sm + 1e-16f);
    for (int k = r0; k < r1e; k++) {
        float er = er1[k];
        float w = g_mw[k];
        al1[k] = 0.5f * expf(lrelu(er) - mf) * isf + 0.5f * expf(lrelu(er * w) - mm) * ism;
    }
}

// block per dst, 128 threads; fp16 gather of h1 (half traffic), fp32 accumulate.
__global__ void k_agg1(const float* __restrict__ b1) {
    int d = blockIdx.x;
    int t = threadIdx.x;          // 0..127 -> channels 4t..4t+3, head = t>>4
    int h = t >> 4;
    const float* al1 = &g_alpha1[h * EPMAX];
    int r0 = g_rowptr[d], r1e = g_rowptr[d + 1];
    float4 acc = make_float4(0.f, 0.f, 0.f, 0.f);
    for (int k = r0; k < r1e; k++) {
        int s = g_srcS[k];
        float a = al1[k];
        uint2 raw = *(const uint2*)&g_h1h[s * INC + t * 4];
        __half2 h01 = *reinterpret_cast<__half2*>(&raw.x);
        __half2 h23 = *reinterpret_cast<__half2*>(&raw.y);
        float2 f01 = __half22float2(h01);
        float2 f23 = __half22float2(h23);
        acc.x += a * f01.x; acc.y += a * f01.y;
        acc.z += a * f23.x; acc.w += a * f23.y;
    }
    float4 bb = *(const float4*)&b1[t * 4];
    float4 o;
    o.x = acc.x + bb.x; o.x = o.x > 0.f ? o.x : expm1f(o.x);
    o.y = acc.y + bb.y; o.y = o.y > 0.f ? o.y : expm1f(o.y);
    o.z = acc.z + bb.z; o.z = o.z > 0.f ? o.z : expm1f(o.z);
    o.w = acc.w + bb.w; o.w = o.w > 0.f ? o.w : expm1f(o.w);
    *(float4*)&g_act1[d * INC + t * 4] = o;
}

// ------------------------- attention layer 2 -------------------------
__global__ void k_scores2(const float* __restrict__ as2, const float* __restrict__ ad2) {
    int n = blockIdx.x * (blockDim.x >> 5) + (threadIdx.x >> 5);
    int lane = threadIdx.x & 31;
    if (n >= NN) return;
    const float* row = &g_h2[n * OUTC];
    float a = 0.f, b = 0.f;
    for (int c = lane; c < OUTC; c += 32) {
        float v = row[c];
        a += v * as2[c];
        b += v * ad2[c];
    }
#pragma unroll
    for (int o = 16; o; o >>= 1) {
        a += __shfl_down_sync(0xffffffffu, a, o);
        b += __shfl_down_sync(0xffffffffu, b, o);
    }
    if (lane == 0) { g_ss2[n] = a; g_sd2[n] = b; }
}

__global__ void k_eraw2(int EP) {
    int i = blockIdx.x * blockDim.x + threadIdx.x;
    if (i >= EP) return;
    g_eraw2[i] = g_ss2[g_srcS[i]] + g_sd2[g_dstS[i]];
}

__global__ void k_softmax2() {
    int d = blockIdx.x * blockDim.x + threadIdx.x;
    if (d >= NN) return;
    int r0 = g_rowptr[d], r1e = g_rowptr[d + 1];
    float mf = -1e30f, mm = -1e30f;
    for (int k = r0; k < r1e; k++) {
        float er = g_eraw2[k];
        float w = g_mw[k];
        mf = fmaxf(mf, lrelu(er));
        mm = fmaxf(mm, lrelu(er * w));
    }
    float sf = 0.f, sm = 0.f;
    for (int k = r0; k < r1e; k++) {
        float er = g_eraw2[k];
        float w = g_mw[k];
        sf += expf(lrelu(er) - mf);
        sm += expf(lrelu(er * w) - mm);
    }
    float isf = 1.f / (sf + 1e-16f), ism = 1.f / (sm + 1e-16f);
    for (int k = r0; k < r1e; k++) {
        float er = g_eraw2[k];
        float w = g_mw[k];
        g_alpha2[k] =
            0.5f * expf(lrelu(er) - mf) * isf + 0.5f * expf(lrelu(er * w) - mm) * ism;
    }
}

// block per dst, 64 threads x float4. out = agg + residual + b2
__global__ void k_agg2(const float* __restrict__ b2, float* __restrict__ out) {
    int d = blockIdx.x;
    int t = threadIdx.x;     // 0..63 -> channels 4t..4t+3
    int r0 = g_rowptr[d], r1e = g_rowptr[d + 1];
    float4 acc = make_float4(0.f, 0.f, 0.f, 0.f);
    for (int k = r0; k < r1e; k++) {
        int s = g_srcS[k];
        float a = g_alpha2[k];
        float4 v = *(const float4*)&g_h2[s * OUTC + t * 4];
        acc.x += a * v.x; acc.y += a * v.y; acc.z += a * v.z; acc.w += a * v.w;
    }
    float4 r = *(const float4*)&g_res[d * OUTC + t * 4];
    float4 bb = *(const float4*)&b2[t * 4];
    float4 o = make_float4(acc.x + r.x + bb.x, acc.y + r.y + bb.y,
                           acc.z + r.z + bb.z, acc.w + r.w + bb.w);
    *(float4*)&out[d * OUTC + t * 4] = o;
}

// ------------------------- launch -------------------------
extern "C" void kernel_launch(void* const* d_in, const int* in_sizes, int n_in,
                              void* d_out, int out_size) {
    const float* x    = (const float*)d_in[0];
    const int*   ei   = (const int*)d_in[1];          // int32 (jax x64 disabled)
    const float* W1   = (const float*)d_in[2];
    const float* as1  = (const float*)d_in[3];
    const float* ad1  = (const float*)d_in[4];
    const float* b1   = (const float*)d_in[5];
    const float* W2   = (const float*)d_in[6];
    const float* as2  = (const float*)d_in[7];
    const float* ad2  = (const float*)d_in[8];
    const float* b2   = (const float*)d_in[9];
    const float* resW2 = (const float*)d_in[10];
    float* out = (float*)d_out;

    int E = in_sizes[1] / 2;
    int EP = E + NN;
    const int* src32 = ei;
    const int* dst32 = ei + E;

    // one-time host-side handles (no device memory)
    static cudaStream_t sB = 0, sC = 0;
    static cudaEvent_t evFork = 0, evBuild = 0, evScat = 0, evCsr = 0, evJoin = 0,
                       evAgg = 0, evRes = 0, evZero = 0;
    if (sB == 0) {
        cudaStreamCreateWithFlags(&sB, cudaStreamNonBlocking);
        cudaStreamCreateWithFlags(&sC, cudaStreamNonBlocking);
        cudaEventCreateWithFlags(&evFork, cudaEventDisableTiming);
        cudaEventCreateWithFlags(&evBuild, cudaEventDisableTiming);
        cudaEventCreateWithFlags(&evScat, cudaEventDisableTiming);
        cudaEventCreateWithFlags(&evCsr, cudaEventDisableTiming);
        cudaEventCreateWithFlags(&evJoin, cudaEventDisableTiming);
        cudaEventCreateWithFlags(&evAgg, cudaEventDisableTiming);
        cudaEventCreateWithFlags(&evRes, cudaEventDisableTiming);
        cudaEventCreateWithFlags(&evZero, cudaEventDisableTiming);
    }

    // ---- fork: feature arm (GEMM1 + scores1) on sB ----
    cudaEventRecord(evFork, 0);
    cudaStreamWaitEvent(sB, evFork, 0);
    {
        dim3 grid(INC / 128, NN / 128, 1);
        k_gemm_tf32<<<grid, 256, 0, sB>>>(x, W1, 0, INC, INC);
    }
    k_scores1<<<(NN * HEADS + 7) / 8, 256, 0, sB>>>(as1, ad1);

    // graph arm on default stream (bitmaps/counters pre-zeroed: loader or previous run's tail)
    k_build<<<(EP + 255) / 256, 256>>>(src32, dst32, E);
    cudaEventRecord(evBuild, 0);

    // csr chain on sC (needs only bitmaps)
    cudaStreamWaitEvent(sC, evBuild, 0);
    k_deg<<<(NN + 7) / 8, 256, 0, sC>>>();
    k_scan2<1><<<2, 1024, 0, sC>>>();
    k_csr_fill<<<NN, WPR, 0, sC>>>();
    cudaEventRecord(evCsr, sC);

    // scatter chain on default (needs only cnt/scnt)
    k_scan2<0><<<2, 1024>>>();
    k_scatter<<<(EP + 255) / 256, 256>>>(src32, dst32, E);
    cudaEventRecord(evScat, 0);

    // spmv + motif need CSR chain too
    cudaStreamWaitEvent(0, evCsr, 0);
    k_spmv<0><<<(NN + 7) / 8, 256>>>();
    k_spmv<1><<<(NN + 7) / 8, 256>>>();
    k_motif<<<NN, 256>>>();

    // tail-zero for the NEXT run, off the critical path (sC: after csr_fill; wait for
    // scan2<0> [reads cnt/scnt] via evScat). Overlaps with motif/softmax/gemm2.
    // Joined back to the origin stream via evZero before the final kernel.
    cudaStreamWaitEvent(sC, evScat, 0);
    k_zero_small<<<(NN * WPR / 4) / 256, 256, 0, sC>>>();
    cudaEventRecord(evZero, sC);

    // eraw1 on sB once scatter (srcS/dstS) and scores1 are done
    cudaStreamWaitEvent(sB, evScat, 0);
    k_eraw1<<<(EP + 255) / 256, 256, 0, sB>>>(EP);
    cudaEventRecord(evJoin, sB);

    // join: softmax1 needs eraw1 (sB) + mw/rowptr (default)
    cudaStreamWaitEvent(0, evJoin, 0);
    k_softmax1<<<(NN * HEADS + 255) / 256, 256>>>();
    k_agg1<<<NN, 128>>>(b1);
    cudaEventRecord(evAgg, 0);

    // ---- layer 2: res-GEMM on sB overlaps scores2/eraw2/softmax2 chain ----
    cudaStreamWaitEvent(sB, evAgg, 0);
    {
        dim3 grid(OUTC / 128, NN / 128, 1);
        k_gemm_tf32<<<grid, 256, 0, sB>>>(x /*unused*/, resW2, 2, OUTC, INC);
    }
    cudaEventRecord(evRes, sB);

    {
        dim3 grid(OUTC / 128, NN / 128, 1);
        k_gemm_tf32<<<grid, 256>>>(x /*unused*/, W2, 1, OUTC, INC);
    }
    k_scores2<<<(NN + 7) / 8, 256>>>(as2, ad2);
    k_eraw2<<<(EP + 255) / 256, 256>>>(EP);
    k_softmax2<<<(NN + 255) / 256, 256>>>();

    // agg2 needs alpha2 (default) + res (sB); also join sC's tail-zero so capture is closed
    cudaStreamWaitEvent(0, evRes, 0);
    cudaStreamWaitEvent(0, evZero, 0);
    k_agg2<<<NN, 64>>>(b2, out);
}

// round 17
// speedup vs baseline: 1.0815x; 1.0815x over previous
#include <cuda_runtime.h>
#include <cuda_fp16.h>
#include <math.h>

#define NN 4096
#define NMASK (NN - 1)
#define INC 512
#define HID 64
#define HEADS 8
#define OUTC 256
#define WPR 128               // bitmap words per row (4096/32)
#define EMAX 131072
#define EPMAX (EMAX + NN)

// ------------------------- device scratch (no allocs allowed) -------------------------
// NOTE: bitmaps + cnt/scnt are zero-initialized at module load and re-zeroed at the
// TAIL of every kernel_launch (k_zero_small), so each run starts clean.
__device__ unsigned g_bmA[NN * WPR];    // adjacency bitmap, row = src
__device__ unsigned g_bmAT[NN * WPR];   // transpose bitmap, row = dst
__device__ int      g_cnt[NN];          // in-degree with duplicates (dst-sorted CSR)
__device__ int      g_scnt[NN];         // out-degree with duplicates (src-sorted CSR)
__device__ int      g_rowptr[NN + 1];
__device__ int      g_cursor[NN];
__device__ int      g_sptr[NN + 1];
__device__ int      g_scursor[NN];
__device__ int      g_srcS[EPMAX];      // edges sorted by dst: src id
__device__ int      g_dstS[EPMAX];      // edges sorted by dst: dst id
__device__ int      g_dS[EPMAX];        // edges sorted by src: dst id
__device__ int      g_eidS[EPMAX];      // edges sorted by src: dst-sorted position
__device__ int      g_odeg[NN], g_ideg[NN];
__device__ int      g_optr[NN + 1], g_iptr[NN + 1];
__device__ int      g_oCSR[EPMAX];      // deduped out-neighbors
__device__ int      g_iCSR[EPMAX];      // deduped in-neighbors
__device__ float    g_r1[NN], g_r2[NN], g_r3[NN];
__device__ float    g_h1[NN * INC];
__device__ __half   g_h1h[NN * INC];    // fp16 shadow of h1 for the agg1 gather
__device__ float    g_act1[NN * INC];
__device__ float    g_h2[NN * OUTC];
__device__ float    g_res[NN * OUTC];
__device__ float    g_ss1[NN * HEADS], g_sd1[NN * HEADS];
__device__ float    g_ss2[NN], g_sd2[NN];
__device__ float    g_eraw1[HEADS * EPMAX];   // [head][edge] planes
__device__ float    g_alpha1[HEADS * EPMAX];  // [head][edge] planes
__device__ float    g_mw[EPMAX];
__device__ float    g_eraw2[EPMAX];
__device__ float    g_alpha2[EPMAX];

// ------------------------- zero kernel (vectorized; runs at TAIL) -------------------------
__global__ void k_zero_small() {
    int i = blockIdx.x * blockDim.x + threadIdx.x;   // 131072 threads
    uint4 z = make_uint4(0u, 0u, 0u, 0u);
    reinterpret_cast<uint4*>(g_bmA)[i] = z;
    reinterpret_cast<uint4*>(g_bmAT)[i] = z;
    if (i < NN) { g_cnt[i] = 0; g_scnt[i] = 0; }
}

// ------------------------- graph build -------------------------
__global__ void k_build(const int* __restrict__ src32,
                        const int* __restrict__ dst32, int E) {
    int i = blockIdx.x * blockDim.x + threadIdx.x;
    int EP = E + NN;
    if (i >= EP) return;
    int s, d;
    if (i < E) { s = src32[i] & NMASK; d = dst32[i] & NMASK; }
    else       { s = d = i - E; }                    // self loops
    atomicOr(&g_bmA[s * WPR + (d >> 5)], 1u << (d & 31));
    atomicOr(&g_bmAT[d * WPR + (s >> 5)], 1u << (s & 31));
    atomicAdd(&g_cnt[d], 1);
    atomicAdd(&g_scnt[s], 1);
}

// degrees from bitmaps, warp per node, one uint4 per lane (coalesced)
__global__ void k_deg() {
    int n = blockIdx.x * (blockDim.x >> 5) + (threadIdx.x >> 5);
    int lane = threadIdx.x & 31;
    if (n >= NN) return;
    uint4 a = reinterpret_cast<const uint4*>(&g_bmA[n * WPR])[lane];
    uint4 b = reinterpret_cast<const uint4*>(&g_bmAT[n * WPR])[lane];
    int co = __popc(a.x) + __popc(a.y) + __popc(a.z) + __popc(a.w);
    int ci = __popc(b.x) + __popc(b.y) + __popc(b.z) + __popc(b.w);
#pragma unroll
    for (int o = 16; o; o >>= 1) {
        co += __shfl_down_sync(0xffffffffu, co, o);
        ci += __shfl_down_sync(0xffffffffu, ci, o);
    }
    if (lane == 0) {
        g_odeg[n] = co;
        g_ideg[n] = ci;
        g_r1[n] = (float)co;
    }
}

// paired scans. WHICH=0: {cnt->rowptr/cursor, scnt->sptr/scursor}. WHICH=1: {odeg->optr, ideg->iptr}.
template <int WHICH>
__global__ void k_scan2() {
    const int* in;
    int* ptr;
    int* cur;
    if (WHICH == 0) {
        if (blockIdx.x == 0) { in = g_cnt;  ptr = g_rowptr; cur = g_cursor; }
        else                 { in = g_scnt; ptr = g_sptr;   cur = g_scursor; }
    } else {
        if (blockIdx.x == 0) { in = g_odeg; ptr = g_optr;   cur = 0; }
        else                 { in = g_ideg; ptr = g_iptr;   cur = 0; }
    }
    __shared__ int sh[1024];
    int t = threadIdx.x;
    int v[4]; int s = 0;
#pragma unroll
    for (int i = 0; i < 4; i++) { v[i] = in[t * 4 + i]; s += v[i]; }
    sh[t] = s;
    __syncthreads();
    for (int off = 1; off < 1024; off <<= 1) {
        int x = (t >= off) ? sh[t - off] : 0;
        __syncthreads();
        sh[t] += x;
        __syncthreads();
    }
    int run = (t == 0) ? 0 : sh[t - 1];
#pragma unroll
    for (int i = 0; i < 4; i++) {
        ptr[t * 4 + i] = run;
        if (cur) cur[t * 4 + i] = run;
        run += v[i];
    }
    if (t == 1023) ptr[NN] = sh[1023];
}

// both counting-sort scatters in one pass; link src-order entry to dst-order pos
__global__ void k_scatter(const int* __restrict__ src32,
                          const int* __restrict__ dst32, int E) {
    int i = blockIdx.x * blockDim.x + threadIdx.x;
    int EP = E + NN;
    if (i >= EP) return;
    int s, d;
    if (i < E) { s = src32[i] & NMASK; d = dst32[i] & NMASK; }
    else       { s = d = i - E; }
    int posD = atomicAdd(&g_cursor[d], 1);
    g_srcS[posD] = s;
    g_dstS[posD] = d;
    int posS = atomicAdd(&g_scursor[s], 1);
    g_dS[posS] = d;
    g_eidS[posS] = posD;
}

// fill deduped CSRs from bitmaps. block per node, thread per word.
__global__ void k_csr_fill() {
    __shared__ int oc, ic;
    int n = blockIdx.x, w = threadIdx.x;
    if (w == 0) { oc = g_optr[n]; ic = g_iptr[n]; }
    __syncthreads();
    unsigned bits = g_bmA[n * WPR + w];
    int c = __popc(bits);
    int p = atomicAdd(&oc, c);
    while (bits) {
        int j = w * 32 + __ffs(bits) - 1;
        bits &= bits - 1;
        g_oCSR[p++] = j;
    }
    bits = g_bmAT[n * WPR + w];
    c = __popc(bits);
    p = atomicAdd(&ic, c);
    while (bits) {
        int j = w * 32 + __ffs(bits) - 1;
        bits &= bits - 1;
        g_iCSR[p++] = j;
    }
}

// ------------------------- motif path -------------------------
template <int PASS>
__global__ void k_spmv() {
    const float* rin  = (PASS == 0) ? g_r1 : g_r2;
    float*       rout = (PASS == 0) ? g_r2 : g_r3;
    int n = blockIdx.x * (blockDim.x >> 5) + (threadIdx.x >> 5);  // warp per node
    int lane = threadIdx.x & 31;
    if (n >= NN) return;
    int o0 = g_optr[n], nm = g_optr[n + 1] - o0;
    float acc = 0.f;
    for (int i = lane; i < nm; i += 32) acc += rin[g_oCSR[o0 + i]];
#pragma unroll
    for (int o = 16; o; o >>= 1) acc += __shfl_down_sync(0xffffffffu, acc, o);
    if (lane == 0) rout[n] = acc;
}

// Fused A^2-row + per-edge A^3: block per source s.
__global__ __launch_bounds__(256) void k_motif() {
    __shared__ int row[NN];    // 16KB
    int s = blockIdx.x;
    for (int i = threadIdx.x; i < NN; i += blockDim.x) row[i] = 0;
    __syncthreads();
    int warp = threadIdx.x >> 5, lane = threadIdx.x & 31;
    int nwarps = blockDim.x >> 5;
    int o0 = g_optr[s], nm = g_optr[s + 1] - o0;
    for (int i = warp; i < nm; i += nwarps) {
        int m = g_oCSR[o0 + i];
        int mo = g_optr[m], mn = g_optr[m + 1] - mo;
        for (int j = lane; j < mn; j += 32)
            atomicAdd(&row[g_oCSR[mo + j]], 1);
    }
    __syncthreads();
    float rs = g_r3[s];
    if (rs < 1.f) rs = 1.f;
    int e0 = g_sptr[s], ne = g_sptr[s + 1] - e0;
    for (int j = warp; j < ne; j += nwarps) {
        int d = g_dS[e0 + j];
        int i0 = g_iptr[d], nk = g_iptr[d + 1] - i0;
        int acc = 0;
        for (int i = lane; i < nk; i += 32) acc += row[g_iCSR[i0 + i]];
#pragma unroll
        for (int o = 16; o; o >>= 1) acc += __shfl_down_sync(0xffffffffu, acc, o);
        if (lane == 0) g_mw[g_eidS[e0 + j]] = (float)acc / rs;
    }
}

// ------------------------- TF32 tensor-core GEMM -------------------------
#define ASTR 36
#define BSTR 136

__device__ __forceinline__ unsigned f2tf32(float f) {
    unsigned u;
    asm("cvt.rna.tf32.f32 %0, %1;" : "=r"(u) : "f"(f));
    return u;
}

// layer 0: A=Aext(x), B=B0(W1), C=g_h1 (+fp16 shadow)
// layer 1: A=g_act1,  B=B0(W2), C=g_h2
// layer 2: A=g_act1,  B=B0(resW2), C=g_res
__global__ __launch_bounds__(256, 1) void k_gemm_tf32(
        const float* __restrict__ Aext,
        const float* __restrict__ B0,
        int layer, int Nn, int K) {
    const float* A;
    const float* B = B0;
    float* C;
    if (layer == 0)      { A = Aext;   C = g_h1; }
    else if (layer == 1) { A = g_act1; C = g_h2; }
    else                 { A = g_act1; C = g_res; }
    __shared__ unsigned As[2][128 * ASTR];
    __shared__ unsigned Bs[2][32 * BSTR];

    int tid = threadIdx.x;
    int lane = tid & 31;
    int warp = tid >> 5;
    int warpM = warp & 1;
    int warpN = warp >> 1;
    int bx = blockIdx.x * 128, by = blockIdx.y * 128;
    int grp = lane >> 2;
    int tig = lane & 3;

    float c[4][4][4];
#pragma unroll
    for (int mi = 0; mi < 4; mi++)
#pragma unroll
        for (int ni = 0; ni < 4; ni++)
#pragma unroll
            for (int r = 0; r < 4; r++) c[mi][ni][r] = 0.f;

    int arow[4], ac4[4], brow[4], bc4[4];
#pragma unroll
    for (int i = 0; i < 4; i++) {
        int idx = tid + i * 256;
        arow[i] = idx >> 3; ac4[i] = idx & 7;
        brow[i] = idx >> 5; bc4[i] = idx & 31;
    }

    auto stageStore = [&](int st, float4 va[4], float4 vb[4]) {
#pragma unroll
        for (int i = 0; i < 4; i++) {
            uint4 t;
            t.x = f2tf32(va[i].x); t.y = f2tf32(va[i].y);
            t.z = f2tf32(va[i].z); t.w = f2tf32(va[i].w);
            *(uint4*)&As[st][arow[i] * ASTR + ac4[i] * 4] = t;
            uint4 u;
            u.x = f2tf32(vb[i].x); u.y = f2tf32(vb[i].y);
            u.z = f2tf32(vb[i].z); u.w = f2tf32(vb[i].w);
            *(uint4*)&Bs[st][brow[i] * BSTR + bc4[i] * 4] = u;
        }
    };

    {
        float4 va[4], vb[4];
#pragma unroll
        for (int i = 0; i < 4; i++) {
            va[i] = *(const float4*)&A[(size_t)(by + arow[i]) * K + ac4[i] * 4];
            vb[i] = *(const float4*)&B[(size_t)brow[i] * Nn + bx + bc4[i] * 4];
        }
        stageStore(0, va, vb);
    }
    __syncthreads();

    int cur = 0;
    for (int k0 = 32; ; k0 += 32) {
        bool more = (k0 < K);
        float4 va[4], vb[4];
        if (more) {
#pragma unroll
            for (int i = 0; i < 4; i++) {
                va[i] = *(const float4*)&A[(size_t)(by + arow[i]) * K + k0 + ac4[i] * 4];
                vb[i] = *(const float4*)&B[(size_t)(k0 + brow[i]) * Nn + bx + bc4[i] * 4];
            }
        }
        const unsigned* as = As[cur];
        const unsigned* bs = Bs[cur];
#pragma unroll
        for (int kk = 0; kk < 32; kk += 8) {
            unsigned af[4][4], bf[4][2];
#pragma unroll
            for (int mi = 0; mi < 4; mi++) {
                int m = warpM * 64 + mi * 16 + grp;
                af[mi][0] = as[m * ASTR + kk + tig];
                af[mi][1] = as[(m + 8) * ASTR + kk + tig];
                af[mi][2] = as[m * ASTR + kk + tig + 4];
                af[mi][3] = as[(m + 8) * ASTR + kk + tig + 4];
            }
#pragma unroll
            for (int ni = 0; ni < 4; ni++) {
                int n = warpN * 32 + ni * 8 + grp;
                bf[ni][0] = bs[(kk + tig) * BSTR + n];
                bf[ni][1] = bs[(kk + tig + 4) * BSTR + n];
            }
#pragma unroll
            for (int mi = 0; mi < 4; mi++)
#pragma unroll
                for (int ni = 0; ni < 4; ni++) {
                    asm volatile(
                        "mma.sync.aligned.m16n8k8.row.col.f32.tf32.tf32.f32 "
                        "{%0,%1,%2,%3}, {%4,%5,%6,%7}, {%8,%9}, {%0,%1,%2,%3};"
                        : "+f"(c[mi][ni][0]), "+f"(c[mi][ni][1]),
                          "+f"(c[mi][ni][2]), "+f"(c[mi][ni][3])
                        : "r"(af[mi][0]), "r"(af[mi][1]),
                          "r"(af[mi][2]), "r"(af[mi][3]),
                          "r"(bf[ni][0]), "r"(bf[ni][1]));
                }
        }
        if (!more) break;
        stageStore(cur ^ 1, va, vb);
        __syncthreads();
        cur ^= 1;
    }

#pragma unroll
    for (int mi = 0; mi < 4; mi++) {
        int m0 = by + warpM * 64 + mi * 16 + grp;
#pragma unroll
        for (int ni = 0; ni < 4; ni++) {
            int n0 = bx + warpN * 32 + ni * 8 + 2 * tig;
            *(float2*)&C[(size_t)m0 * Nn + n0] = make_float2(c[mi][ni][0], c[mi][ni][1]);
            *(float2*)&C[(size_t)(m0 + 8) * Nn + n0] = make_float2(c[mi][ni][2], c[mi][ni][3]);
            if (layer == 0) {   // fp16 shadow of h1 for agg1 gather
                *(__half2*)&g_h1h[(size_t)m0 * INC + n0] =
                    __floats2half2_rn(c[mi][ni][0], c[mi][ni][1]);
                *(__half2*)&g_h1h[(size_t)(m0 + 8) * INC + n0] =
                    __floats2half2_rn(c[mi][ni][2], c[mi][ni][3]);
            }
        }
    }
}

// ------------------------- attention layer 1 -------------------------
__global__ void k_scores1(const float* __restrict__ as1, const float* __restrict__ ad1) {
    int idx = blockIdx.x * (blockDim.x >> 5) + (threadIdx.x >> 5);  // warp per (n,h)
    int lane = threadIdx.x & 31;
    if (idx >= NN * HEADS) return;
    int n = idx >> 3, h = idx & 7;
    const float* row = &g_h1[n * INC + h * HID];
    float a = 0.f, b = 0.f;
    for (int c = lane; c < HID; c += 32) {
        float v = row[c];
        a += v * as1[h * HID + c];
        b += v * ad1[h * HID + c];
    }
#pragma unroll
    for (int o = 16; o; o >>= 1) {
        a += __shfl_down_sync(0xffffffffu, a, o);
        b += __shfl_down_sync(0xffffffffu, b, o);
    }
    if (lane == 0) { g_ss1[idx] = a; g_sd1[idx] = b; }
}

// thread per edge; writes 8 head-planes (coalesced within each plane)
__global__ void k_eraw1(int EP) {
    int e = blockIdx.x * blockDim.x + threadIdx.x;
    if (e >= EP) return;
    int s = g_srcS[e], d = g_dstS[e];
    float4 sa = *(const float4*)&g_ss1[s * HEADS];
    float4 sb = *(const float4*)&g_ss1[s * HEADS + 4];
    float4 da = *(const float4*)&g_sd1[d * HEADS];
    float4 db = *(const float4*)&g_sd1[d * HEADS + 4];
    g_eraw1[0 * EPMAX + e] = sa.x + da.x;
    g_eraw1[1 * EPMAX + e] = sa.y + da.y;
    g_eraw1[2 * EPMAX + e] = sa.z + da.z;
    g_eraw1[3 * EPMAX + e] = sa.w + da.w;
    g_eraw1[4 * EPMAX + e] = sb.x + db.x;
    g_eraw1[5 * EPMAX + e] = sb.y + db.y;
    g_eraw1[6 * EPMAX + e] = sb.z + db.z;
    g_eraw1[7 * EPMAX + e] = sb.w + db.w;
}

__device__ __forceinline__ float lrelu(float x) { return x > 0.f ? x : 0.2f * x; }

// warp per (h,d) row: lanes stride the edge range, shuffle reductions.
__global__ void k_softmax1() {
    int idx = blockIdx.x * (blockDim.x >> 5) + (threadIdx.x >> 5);
    int lane = threadIdx.x & 31;
    if (idx >= NN * HEADS) return;
    int h = idx >> 12;            // idx / NN
    int d = idx & NMASK;
    const float* er1 = &g_eraw1[h * EPMAX];
    float* al1 = &g_alpha1[h * EPMAX];
    int r0 = g_rowptr[d], r1e = g_rowptr[d + 1];
    float mf = -1e30f, mm = -1e30f;
    for (int k = r0 + lane; k < r1e; k += 32) {
        float er = er1[k];
        float w = g_mw[k];
        mf = fmaxf(mf, lrelu(er));
        mm = fmaxf(mm, lrelu(er * w));
    }
#pragma unroll
    for (int o = 16; o; o >>= 1) {
        mf = fmaxf(mf, __shfl_xor_sync(0xffffffffu, mf, o));
        mm = fmaxf(mm, __shfl_xor_sync(0xffffffffu, mm, o));
    }
    float sf = 0.f, sm = 0.f;
    for (int k = r0 + lane; k < r1e; k += 32) {
        float er = er1[k];
        float w = g_mw[k];
        sf += expf(lrelu(er) - mf);
        sm += expf(lrelu(er * w) - mm);
    }
#pragma unroll
    for (int o = 16; o; o >>= 1) {
        sf += __shfl_xor_sync(0xffffffffu, sf, o);
        sm += __shfl_xor_sync(0xffffffffu, sm, o);
    }
    float isf = 0.5f / (sf + 1e-16f), ism = 0.5f / (sm + 1e-16f);
    for (int k = r0 + lane; k < r1e; k += 32) {
        float er = er1[k];
        float w = g_mw[k];
        al1[k] = expf(lrelu(er) - mf) * isf + expf(lrelu(er * w) - mm) * ism;
    }
}

// block per dst, 256 threads = 128 channels x 2 edge-phases; smem combine.
// fp16 gather of h1, fp32 accumulate. act1 = elu(agg + b1)
__global__ void k_agg1(const float* __restrict__ b1) {
    __shared__ float4 sacc[128];
    int d = blockIdx.x;
    int t = threadIdx.x;          // 0..255
    int c = t & 127;              // channel group (4 channels)
    int kg = t >> 7;              // edge phase 0/1
    int h = c >> 4;
    const float* al1 = &g_alpha1[h * EPMAX];
    int r0 = g_rowptr[d], r1e = g_rowptr[d + 1];
    float4 acc = make_float4(0.f, 0.f, 0.f, 0.f);
    for (int k = r0 + kg; k < r1e; k += 2) {
        int s = g_srcS[k];
        float a = al1[k];
        uint2 raw = *(const uint2*)&g_h1h[s * INC + c * 4];
        __half2 h01 = *reinterpret_cast<__half2*>(&raw.x);
        __half2 h23 = *reinterpret_cast<__half2*>(&raw.y);
        float2 f01 = __half22float2(h01);
        float2 f23 = __half22float2(h23);
        acc.x += a * f01.x; acc.y += a * f01.y;
        acc.z += a * f23.x; acc.w += a * f23.y;
    }
    if (kg == 1) sacc[c] = acc;
    __syncthreads();
    if (kg == 0) {
        float4 o2 = sacc[c];
        acc.x += o2.x; acc.y += o2.y; acc.z += o2.z; acc.w += o2.w;
        float4 bb = *(const float4*)&b1[c * 4];
        float4 o;
        o.x = acc.x + bb.x; o.x = o.x > 0.f ? o.x : expm1f(o.x);
        o.y = acc.y + bb.y; o.y = o.y > 0.f ? o.y : expm1f(o.y);
        o.z = acc.z + bb.z; o.z = o.z > 0.f ? o.z : expm1f(o.z);
        o.w = acc.w + bb.w; o.w = o.w > 0.f ? o.w : expm1f(o.w);
        *(float4*)&g_act1[d * INC + c * 4] = o;
    }
}

// ------------------------- attention layer 2 -------------------------
__global__ void k_scores2(const float* __restrict__ as2, const float* __restrict__ ad2) {
    int n = blockIdx.x * (blockDim.x >> 5) + (threadIdx.x >> 5);
    int lane = threadIdx.x & 31;
    if (n >= NN) return;
    const float* row = &g_h2[n * OUTC];
    float a = 0.f, b = 0.f;
    for (int c = lane; c < OUTC; c += 32) {
        float v = row[c];
        a += v * as2[c];
        b += v * ad2[c];
    }
#pragma unroll
    for (int o = 16; o; o >>= 1) {
        a += __shfl_down_sync(0xffffffffu, a, o);
        b += __shfl_down_sync(0xffffffffu, b, o);
    }
    if (lane == 0) { g_ss2[n] = a; g_sd2[n] = b; }
}

__global__ void k_eraw2(int EP) {
    int i = blockIdx.x * blockDim.x + threadIdx.x;
    if (i >= EP) return;
    g_eraw2[i] = g_ss2[g_srcS[i]] + g_sd2[g_dstS[i]];
}

// warp per dst row: lanes stride the edge range, shuffle reductions.
__global__ void k_softmax2() {
    int d = blockIdx.x * (blockDim.x >> 5) + (threadIdx.x >> 5);
    int lane = threadIdx.x & 31;
    if (d >= NN) return;
    int r0 = g_rowptr[d], r1e = g_rowptr[d + 1];
    float mf = -1e30f, mm = -1e30f;
    for (int k = r0 + lane; k < r1e; k += 32) {
        float er = g_eraw2[k];
        float w = g_mw[k];
        mf = fmaxf(mf, lrelu(er));
        mm = fmaxf(mm, lrelu(er * w));
    }
#pragma unroll
    for (int o = 16; o; o >>= 1) {
        mf = fmaxf(mf, __shfl_xor_sync(0xffffffffu, mf, o));
        mm = fmaxf(mm, __shfl_xor_sync(0xffffffffu, mm, o));
    }
    float sf = 0.f, sm = 0.f;
    for (int k = r0 + lane; k < r1e; k += 32) {
        float er = g_eraw2[k];
        float w = g_mw[k];
        sf += expf(lrelu(er) - mf);
        sm += expf(lrelu(er * w) - mm);
    }
#pragma unroll
    for (int o = 16; o; o >>= 1) {
        sf += __shfl_xor_sync(0xffffffffu, sf, o);
        sm += __shfl_xor_sync(0xffffffffu, sm, o);
    }
    float isf = 0.5f / (sf + 1e-16f), ism = 0.5f / (sm + 1e-16f);
    for (int k = r0 + lane; k < r1e; k += 32) {
        float er = g_eraw2[k];
        float w = g_mw[k];
        g_alpha2[k] = expf(lrelu(er) - mf) * isf + expf(lrelu(er * w) - mm) * ism;
    }
}

// block per dst, 256 threads = 64 channels x 4 edge-phases; smem combine.
__global__ void k_agg2(const float* __restrict__ b2, float* __restrict__ out) {
    __shared__ float4 sacc[3][64];
    int d = blockIdx.x;
    int t = threadIdx.x;     // 0..255
    int c = t & 63;          // channel group
    int kg = t >> 6;         // 0..3
    int r0 = g_rowptr[d], r1e = g_rowptr[d + 1];
    float4 acc = make_float4(0.f, 0.f, 0.f, 0.f);
    for (int k = r0 + kg; k < r1e; k += 4) {
        int s = g_srcS[k];
        float a = g_alpha2[k];
        float4 v = *(const float4*)&g_h2[s * OUTC + c * 4];
        acc.x += a * v.x; acc.y += a * v.y; acc.z += a * v.z; acc.w += a * v.w;
    }
    if (kg > 0) sacc[kg - 1][c] = acc;
    __syncthreads();
    if (kg == 0) {
#pragma unroll
        for (int p = 0; p < 3; p++) {
            float4 o2 = sacc[p][c];
            acc.x += o2.x; acc.y += o2.y; acc.z += o2.z; acc.w += o2.w;
        }
        float4 r = *(const float4*)&g_res[d * OUTC + c * 4];
        float4 bb = *(const float4*)&b2[c * 4];
        float4 o = make_float4(acc.x + r.x + bb.x, acc.y + r.y + bb.y,
                               acc.z + r.z + bb.z, acc.w + r.w + bb.w);
        *(float4*)&out[d * OUTC + c * 4] = o;
    }
}

// ------------------------- launch -------------------------
extern "C" void kernel_launch(void* const* d_in, const int* in_sizes, int n_in,
                              void* d_out, int out_size) {
    const float* x    = (const float*)d_in[0];
    const int*   ei   = (const int*)d_in[1];          // int32 (jax x64 disabled)
    const float* W1   = (const float*)d_in[2];
    const float* as1  = (const float*)d_in[3];
    const float* ad1  = (const float*)d_in[4];
    const float* b1   = (const float*)d_in[5];
    const float* W2   = (const float*)d_in[6];
    const float* as2  = (const float*)d_in[7];
    const float* ad2  = (const float*)d_in[8];
    const float* b2   = (const float*)d_in[9];
    const float* resW2 = (const float*)d_in[10];
    float* out = (float*)d_out;

    int E = in_sizes[1] / 2;
    int EP = E + NN;
    const int* src32 = ei;
    const int* dst32 = ei + E;

    // one-time host-side handles (no device memory)
    static cudaStream_t sB = 0, sC = 0;
    static cudaEvent_t evFork = 0, evBuild = 0, evScat = 0, evCsr = 0, evJoin = 0,
                       evAgg = 0, evRes = 0, evZero = 0;
    if (sB == 0) {
        cudaStreamCreateWithFlags(&sB, cudaStreamNonBlocking);
        cudaStreamCreateWithFlags(&sC, cudaStreamNonBlocking);
        cudaEventCreateWithFlags(&evFork, cudaEventDisableTiming);
        cudaEventCreateWithFlags(&evBuild, cudaEventDisableTiming);
        cudaEventCreateWithFlags(&evScat, cudaEventDisableTiming);
        cudaEventCreateWithFlags(&evCsr, cudaEventDisableTiming);
        cudaEventCreateWithFlags(&evJoin, cudaEventDisableTiming);
        cudaEventCreateWithFlags(&evAgg, cudaEventDisableTiming);
        cudaEventCreateWithFlags(&evRes, cudaEventDisableTiming);
        cudaEventCreateWithFlags(&evZero, cudaEventDisableTiming);
    }

    // ---- fork: feature arm (GEMM1 + scores1) on sB ----
    cudaEventRecord(evFork, 0);
    cudaStreamWaitEvent(sB, evFork, 0);
    {
        dim3 grid(INC / 128, NN / 128, 1);
        k_gemm_tf32<<<grid, 256, 0, sB>>>(x, W1, 0, INC, INC);
    }
    k_scores1<<<(NN * HEADS + 7) / 8, 256, 0, sB>>>(as1, ad1);

    // graph arm on default stream (bitmaps/counters pre-zeroed: loader or previous run's tail)
    k_build<<<(EP + 255) / 256, 256>>>(src32, dst32, E);
    cudaEventRecord(evBuild, 0);

    // csr chain on sC (needs only bitmaps)
    cudaStreamWaitEvent(sC, evBuild, 0);
    k_deg<<<(NN + 7) / 8, 256, 0, sC>>>();
    k_scan2<1><<<2, 1024, 0, sC>>>();
    k_csr_fill<<<NN, WPR, 0, sC>>>();
    cudaEventRecord(evCsr, sC);

    // scatter chain on default (needs only cnt/scnt)
    k_scan2<0><<<2, 1024>>>();
    k_scatter<<<(EP + 255) / 256, 256>>>(src32, dst32, E);
    cudaEventRecord(evScat, 0);

    // spmv + motif need CSR chain too
    cudaStreamWaitEvent(0, evCsr, 0);
    k_spmv<0><<<(NN + 7) / 8, 256>>>();
    k_spmv<1><<<(NN + 7) / 8, 256>>>();
    k_motif<<<NN, 256>>>();

    // tail-zero for the NEXT run, off the critical path; joined via evZero before agg2
    cudaStreamWaitEvent(sC, evScat, 0);
    k_zero_small<<<(NN * WPR / 4) / 256, 256, 0, sC>>>();
    cudaEventRecord(evZero, sC);

    // eraw1 on sB once scatter (srcS/dstS) and scores1 are done
    cudaStreamWaitEvent(sB, evScat, 0);
    k_eraw1<<<(EP + 255) / 256, 256, 0, sB>>>(EP);
    cudaEventRecord(evJoin, sB);

    // join: softmax1 needs eraw1 (sB) + mw/rowptr (default)
    cudaStreamWaitEvent(0, evJoin, 0);
    k_softmax1<<<(NN * HEADS + 7) / 8, 256>>>();
    k_agg1<<<NN, 256>>>(b1);
    cudaEventRecord(evAgg, 0);

    // ---- layer 2: res-GEMM on sB overlaps scores2/eraw2/softmax2 chain ----
    cudaStreamWaitEvent(sB, evAgg, 0);
    {
        dim3 grid(OUTC / 128, NN / 128, 1);
        k_gemm_tf32<<<grid, 256, 0, sB>>>(x /*unused*/, resW2, 2, OUTC, INC);
    }
    cudaEventRecord(evRes, sB);

    {
        dim3 grid(OUTC / 128, NN / 128, 1);
        k_gemm_tf32<<<grid, 256>>>(x /*unused*/, W2, 1, OUTC, INC);
    }
    k_scores2<<<(NN + 7) / 8, 256>>>(as2, ad2);
    k_eraw2<<<(EP + 255) / 256, 256>>>(EP);
    k_softmax2<<<(NN + 7) / 8, 256>>>();

    // agg2 needs alpha2 (default) + res (sB); also join sC's tail-zero so capture is closed
    cudaStreamWaitEvent(0, evRes, 0);
    cudaStreamWaitEvent(0, evZero, 0);
    k_agg2<<<NN, 256>>>(b2, out);
}